// round 8
// baseline (speedup 1.0000x reference)
#include <cuda_runtime.h>
#include <cuda_bf16.h>
#include <cstdint>

// B=8, K=4096, M=4096, L=8192, D=512 fp32.
// out[b, keep_ids[b,k], :] = inputs[b,k,:] ; out[b, mask_ids[b,m], :] = mask_embedding
// keep/mask ids partition [0,L) -> every output row written exactly once.
//
// R7: one warp per 2 rows; front-batch all 8 float4 loads (MLP_p1 = 8/thread)
// before issuing the 8 stores. Streaming (.cs) on once-touched bulk data,
// cached (__ldg) on the hot embedding + indices.

#define B_DIM 8
#define K_DIM 4096
#define M_DIM 4096
#define L_DIM (K_DIM + M_DIM)
#define D_DIM 512
#define VEC4_PER_ROW (D_DIM / 4)        // 128
#define ROWS_PER_WARP 2
#define WARPS_PER_BLOCK 8
#define ROWS_PER_BLOCK (ROWS_PER_WARP * WARPS_PER_BLOCK)   // 16
#define THREADS (32 * WARPS_PER_BLOCK)                     // 256

__global__ __launch_bounds__(THREADS)
void maskfiller_scatter_kernel(const float4* __restrict__ inputs,        // [B, K, 128]
                               const int*    __restrict__ mask_ids,     // [B, M]
                               const int*    __restrict__ keep_ids,     // [B, K]
                               const float4* __restrict__ mask_emb,     // [128]
                               float4*       __restrict__ out)          // [B, L, 128]
{
    const int warp = threadIdx.x >> 5;
    const int lane = threadIdx.x & 31;
    const int row0 = blockIdx.x * ROWS_PER_BLOCK + warp * ROWS_PER_WARP;
    const int row1 = row0 + 1;

    const int b0 = row0 / L_DIM;
    const int r0 = row0 - b0 * L_DIM;
    const int b1 = row1 / L_DIM;
    const int r1 = row1 - b1 * L_DIM;

    const bool keep0 = (r0 < K_DIM);
    const bool keep1 = (r1 < K_DIM);

    // Destination rows (warp-uniform index loads; hot in L1/L2).
    const int dst0 = keep0 ? __ldg(&keep_ids[b0 * K_DIM + r0])
                           : __ldg(&mask_ids[b0 * M_DIM + (r0 - K_DIM)]);
    const int dst1 = keep1 ? __ldg(&keep_ids[b1 * K_DIM + r1])
                           : __ldg(&mask_ids[b1 * M_DIM + (r1 - K_DIM)]);

    float4* dp0 = out + ((size_t)b0 * L_DIM + dst0) * VEC4_PER_ROW + lane;
    float4* dp1 = out + ((size_t)b1 * L_DIM + dst1) * VEC4_PER_ROW + lane;

    // ---- front-batch all loads (up to 8 independent DRAM loads in flight) ----
    float4 a0, a1, a2, a3, c0, c1, c2, c3;

    if (keep0) {
        const float4* s0 = inputs + ((size_t)b0 * K_DIM + r0) * VEC4_PER_ROW + lane;
        a0 = __ldcs(s0 +  0);
        a1 = __ldcs(s0 + 32);
        a2 = __ldcs(s0 + 64);
        a3 = __ldcs(s0 + 96);
    } else {
        a0 = __ldg(mask_emb + lane +  0);
        a1 = __ldg(mask_emb + lane + 32);
        a2 = __ldg(mask_emb + lane + 64);
        a3 = __ldg(mask_emb + lane + 96);
    }

    if (keep1) {
        const float4* s1 = inputs + ((size_t)b1 * K_DIM + r1) * VEC4_PER_ROW + lane;
        c0 = __ldcs(s1 +  0);
        c1 = __ldcs(s1 + 32);
        c2 = __ldcs(s1 + 64);
        c3 = __ldcs(s1 + 96);
    } else {
        c0 = __ldg(mask_emb + lane +  0);
        c1 = __ldg(mask_emb + lane + 32);
        c2 = __ldg(mask_emb + lane + 64);
        c3 = __ldg(mask_emb + lane + 96);
    }

    // ---- stores (issue-cost only) ----
    __stcs(dp0 +  0, a0);
    __stcs(dp0 + 32, a1);
    __stcs(dp0 + 64, a2);
    __stcs(dp0 + 96, a3);
    __stcs(dp1 +  0, c0);
    __stcs(dp1 + 32, c1);
    __stcs(dp1 + 64, c2);
    __stcs(dp1 + 96, c3);
}

extern "C" void kernel_launch(void* const* d_in, const int* in_sizes, int n_in,
                              void* d_out, int out_size)
{
    // metadata order: inputs(f32), mask_position_ids(i32), keep_position_ids(i32),
    //                 mask_embedding(f32), [axis]
    const float4* inputs   = (const float4*)d_in[0];
    const int*    mask_ids = (const int*)d_in[1];
    const int*    keep_ids = (const int*)d_in[2];
    const float4* mask_emb = (const float4*)d_in[3];
    float4*       out      = (float4*)d_out;

    const int total_rows = B_DIM * L_DIM;                  // 65536
    const int blocks     = total_rows / ROWS_PER_BLOCK;    // 4096
    maskfiller_scatter_kernel<<<blocks, THREADS>>>(
        inputs, mask_ids, keep_ids, mask_emb, out);
}